// round 6
// baseline (speedup 1.0000x reference)
#include <cuda_runtime.h>
#include <cuda_bf16.h>

// x (64, 96, 8, 8) fp32 -> out (64, 96, 96, 8, 8, 2) fp32
// out[b,i,j,c1,c2,0] = x[b,i,c1,c2]; out[b,i,j,c1,c2,1] = x[b,j,c1,c2]
//
// One block per (b,i) pair. Thread tid = jl*32 + k2:
//   - loads xi float2 at k2 ONCE (reused for all 96 j)
//   - iterates t=0..11 over j = jl + 8*t, loading xj float2 and storing
//     one interleaved float4 {xi.x, xj.x, xi.y, xj.y}.
// Warp (32 consecutive k2, same j): 256B coalesced load, 512B coalesced store.

#define GS 96
#define BLK 64            // 8*8 floats per group block
#define F4  32            // float4 per (b,i,j)

__global__ __launch_bounds__(256)
void gcom_kernel(const float* __restrict__ x, float4* __restrict__ out)
{
    unsigned bi = blockIdx.x;              // b*96 + i, 0..6143
    unsigned b  = bi / GS;
    unsigned i  = bi - b * GS;

    unsigned tid = threadIdx.x;
    unsigned k2  = tid & 31u;              // float2 index within the 64-float block
    unsigned jl  = tid >> 5;               // 0..7 (j lane)

    const float2* xrow = (const float2*)(x + (size_t)b * GS * BLK);

    // xi: loaded once, reused across all 96 j
    float2 a = __ldg(xrow + i * F4 + k2);

    const float2* xj = xrow + jl * F4 + k2;
    float4* o = out + (size_t)bi * (GS * F4) + jl * F4 + k2;

#pragma unroll
    for (int t = 0; t < 12; ++t) {
        float2 c = __ldg(xj + t * (8 * F4));
        float4 v = make_float4(a.x, c.x, a.y, c.y);
        __stcs(o + t * (8 * F4), v);       // streaming store: output never re-read
    }
}

extern "C" void kernel_launch(void* const* d_in, const int* in_sizes, int n_in,
                              void* d_out, int out_size)
{
    const float* x = (const float*)d_in[0];
    float4* out = (float4*)d_out;

    // 64 * 96 = 6144 blocks; each writes 96*32 float4 = 48 KB of output.
    gcom_kernel<<<64 * GS, 256>>>(x, out);
}

// round 7
// speedup vs baseline: 1.4715x; 1.4715x over previous
#include <cuda_runtime.h>
#include <cuda_bf16.h>

// x (64, 96, 8, 8) fp32 -> out (64, 96, 96, 8, 8, 2) fp32
// out[b,i,j,c1,c2,0] = x[b,i,c1,c2]; out[b,i,j,c1,c2,1] = x[b,j,c1,c2]
//
// Block = (b, i, jt) covering 32 consecutive j's.
//   warp w (0..7) handles j = jt*32 + w*4 + {0,1,2,3}; lane = k2 (0..31).
// Per thread: 1 xi float2 load (reused), 4 independent xj loads, 4 independent
// 512B-coalesced float4 stores. Loads hoisted above stores for MLP.

#define GS  96
#define BLK 64            // 8*8 floats per group block
#define F4  32            // float4 per (b,i,j) pair
#define JT  3             // j-tiles per (b,i): 3 * 32 = 96

__global__ __launch_bounds__(256)
void gcom_kernel(const float* __restrict__ x, float4* __restrict__ out)
{
    unsigned blk = blockIdx.x;             // (b*96 + i)*3 + jt
    unsigned jt  = blk % JT;
    unsigned bi  = blk / JT;               // b*96 + i
    unsigned b   = bi / GS;
    unsigned i   = bi - b * GS;

    unsigned lane = threadIdx.x & 31u;     // k2: float2 index within 64-float block
    unsigned w    = threadIdx.x >> 5;      // warp 0..7
    unsigned j0   = jt * 32 + w * 4;       // first of 4 j's for this warp

    const float2* xrow = (const float2*)(x + (size_t)b * GS * BLK);

    // All loads issued up front (independent; xi reused for 4 stores).
    float2 a  = __ldg(xrow + i * F4 + lane);
    const float2* xj = xrow + j0 * F4 + lane;
    float2 c0 = __ldg(xj);
    float2 c1 = __ldg(xj + F4);
    float2 c2 = __ldg(xj + 2 * F4);
    float2 c3 = __ldg(xj + 3 * F4);

    float4* o = out + (size_t)bi * (GS * F4) + j0 * F4 + lane;
    o[0]      = make_float4(a.x, c0.x, a.y, c0.y);
    o[F4]     = make_float4(a.x, c1.x, a.y, c1.y);
    o[2 * F4] = make_float4(a.x, c2.x, a.y, c2.y);
    o[3 * F4] = make_float4(a.x, c3.x, a.y, c3.y);
}

extern "C" void kernel_launch(void* const* d_in, const int* in_sizes, int n_in,
                              void* d_out, int out_size)
{
    const float* x = (const float*)d_in[0];
    float4* out = (float4*)d_out;

    // 64 * 96 * 3 = 18432 blocks; each writes 32 * 512B = 16KB of output.
    gcom_kernel<<<64 * GS * JT, 256>>>(x, out);
}